// round 8
// baseline (speedup 1.0000x reference)
#include <cuda_runtime.h>

#define Pn   64
#define Sn   4096
#define Dn   128
#define TM   32          // sample rows per block
#define NTHR 128
#define APAD 132         // padded activation row stride (floats) -> conflict-free

// -------- persistent scratch (no allocs allowed) --------
__device__ float gK[Pn * Dn];
__device__ float gV[Pn * Dn];
__device__ float gWoT[Dn * Dn];
__device__ float gWfcT[Dn * Dn];
__device__ float gA[Dn * Dn];     // folded Wq * K^T / 8   (scores = x @ gA + gc)
__device__ float gB[Dn * Dn];     // folded V * Wo^T       (h = alpha @ gB + bo)
__device__ float gc[Dn];          // folded bq * K^T / 8

// ============================================================
// Precompute 1: K = proxies @ Wk^T + bk ; V = proxies @ Wv^T + bv
// grid 64 (one proxy per block), 128 threads (one output dim each)
// ============================================================
__global__ void pre_kv_kernel(const float* __restrict__ proxies,
                              const float* __restrict__ Wk, const float* __restrict__ bk,
                              const float* __restrict__ Wv, const float* __restrict__ bv) {
    __shared__ float pr[Dn];
    const int p = blockIdx.x, t = threadIdx.x;
    pr[t] = proxies[p * Dn + t];
    __syncthreads();
    const float* wk = Wk + t * Dn;
    const float* wv = Wv + t * Dn;
    float a = 0.f, b = 0.f;
#pragma unroll 16
    for (int j = 0; j < Dn; j++) { a += pr[j] * wk[j]; b += pr[j] * wv[j]; }
    gK[p * Dn + t] = a + bk[t];
    gV[p * Dn + t] = b + bv[t];
}

// ============================================================
// Precompute 2: transpose Wo and Wfc (coalesced reads)
// grid 128, 128 threads
// ============================================================
__global__ void pre_tr_kernel(const float* __restrict__ Wo,
                              const float* __restrict__ Wfc) {
    const int b = blockIdx.x, t = threadIdx.x;
    gWoT [t * Dn + b] = Wo [b * Dn + t];   // WoT[d][j]  = Wo[j][d]
    gWfcT[t * Dn + b] = Wfc[b * Dn + t];   // WfcT[d][j] = Wfc[j][d]
}

// ============================================================
// Precompute 3: fold projections into per-proxy matrices.
//   col = h*64 + p
//   gA[d][col] = (1/8) * sum_j Wq[h*64+j][d] * K[p][h*64+j]
//   gc[col]    = (1/8) * sum_j bq[h*64+j]    * K[p][h*64+j]
//   gB[col][j] =         sum_j' V[p][h*64+j'] * Wo[j][h*64+j']
// grid 128 (one col per block), 128 threads
// ============================================================
__global__ void pre_ab_kernel(const float* __restrict__ Wq,
                              const float* __restrict__ bq) {
    __shared__ float kh[64], vh[64], part[64];
    const int col = blockIdx.x, t = threadIdx.x;
    const int h = col >> 6, p = col & 63;
    if (t < 64) {
        float kv = gK[p * Dn + h * 64 + t];
        kh[t] = kv;
        vh[t] = gV[p * Dn + h * 64 + t];
        part[t] = bq[h * 64 + t] * kv;
    }
    __syncthreads();
    float a = 0.f;
#pragma unroll 16
    for (int j = 0; j < 64; j++) a += Wq[(h * 64 + j) * Dn + t] * kh[j];   // coalesced over t
    gA[t * Dn + col] = a * 0.125f;
    float bs = 0.f;
#pragma unroll 16
    for (int j = 0; j < 64; j++) bs += vh[j] * gWoT[(h * 64 + j) * Dn + t]; // coalesced over t
    gB[col * Dn + t] = bs;
    if (t == 0) {
        float cs = 0.f;
        for (int j = 0; j < 64; j++) cs += part[j];
        gc[col] = cs * 0.125f;
    }
}

// ============================================================
// Main fused kernel: 3 chained 32x128x128 GEMM stages + softmax.
// 128 threads: rg = tid>>4 (8 row groups of 4), cg = tid&15 (16 col groups).
// Each thread: 4 rows x 8 cols register tile (cols c0..c0+3 and 64+c0..64+c0+3).
// ============================================================
__device__ __forceinline__ void gemm_tile(const float* __restrict__ Xs,   // [TM][APAD]
                                          const float* __restrict__ Ws,   // [128][128]
                                          float acc[4][8], int rbase, int c0) {
#pragma unroll
    for (int i = 0; i < 4; i++)
#pragma unroll
        for (int j = 0; j < 8; j++) acc[i][j] = 0.f;

    const float* xr = Xs + rbase * APAD;
#pragma unroll 8
    for (int k = 0; k < Dn; k++) {
        float xv[4];
#pragma unroll
        for (int i = 0; i < 4; i++) xv[i] = xr[i * APAD + k];   // broadcast, conflict-free
        float4 w0 = *reinterpret_cast<const float4*>(Ws + k * Dn + c0);
        float4 w1 = *reinterpret_cast<const float4*>(Ws + k * Dn + 64 + c0);
        float wv[8] = {w0.x, w0.y, w0.z, w0.w, w1.x, w1.y, w1.z, w1.w};
#pragma unroll
        for (int i = 0; i < 4; i++)
#pragma unroll
            for (int j = 0; j < 8; j++) acc[i][j] += xv[i] * wv[j];
    }
}

__device__ __forceinline__ void load_weight(const float* __restrict__ gW, float* Wbuf, int tid) {
    const float4* g = reinterpret_cast<const float4*>(gW);
    float4* s = reinterpret_cast<float4*>(Wbuf);
#pragma unroll
    for (int i = 0; i < 32; i++) s[tid + i * NTHR] = g[tid + i * NTHR];
}

__global__ __launch_bounds__(NTHR) void gnn_main_kernel(
    const float* __restrict__ x,
    const float* __restrict__ bo, const float* __restrict__ bfc,
    float* __restrict__ outP, float* __restrict__ outH)
{
    extern __shared__ float smem[];
    float* act0 = smem;                       // TM*APAD : x tile, later h tile
    float* act1 = smem + TM * APAD;           // TM*APAD : scores -> alpha
    float* Wbuf = smem + 2 * TM * APAD;       // 128*128 : A, then B, then WfcT

    const int tid   = threadIdx.x;
    const int row0  = blockIdx.x * TM;
    const int rg    = tid >> 4;
    const int cg    = tid & 15;
    const int rbase = rg * 4;
    const int c0    = cg * 4;

    // -------- load x tile (row-major, padded) + A --------
    {
        const float4* xg = reinterpret_cast<const float4*>(x + (size_t)row0 * Dn);
#pragma unroll
        for (int i = 0; i < 8; i++) {
            int idx = tid + i * NTHR;          // float4 index within 32x128 tile
            int r = idx >> 5, c4 = idx & 31;
            float4 v = xg[idx];
            *reinterpret_cast<float4*>(act0 + r * APAD + c4 * 4) = v;
        }
        load_weight(gA, Wbuf, tid);
    }
    __syncthreads();

    float acc[4][8];

    // -------- stage 1: scores = x @ A + c --------
    gemm_tile(act0, Wbuf, acc, rbase, c0);
    {
        float4 cv0 = *reinterpret_cast<const float4*>(gc + c0);
        float4 cv1 = *reinterpret_cast<const float4*>(gc + 64 + c0);
#pragma unroll
        for (int i = 0; i < 4; i++) {
            float4 s0 = make_float4(acc[i][0] + cv0.x, acc[i][1] + cv0.y,
                                    acc[i][2] + cv0.z, acc[i][3] + cv0.w);
            float4 s1 = make_float4(acc[i][4] + cv1.x, acc[i][5] + cv1.y,
                                    acc[i][6] + cv1.z, acc[i][7] + cv1.w);
            *reinterpret_cast<float4*>(act1 + (rbase + i) * APAD + c0)      = s0;
            *reinterpret_cast<float4*>(act1 + (rbase + i) * APAD + 64 + c0) = s1;
        }
    }
    __syncthreads();

    // -------- load B (all threads) + per-(row,head) softmax over 64 proxies --------
    load_weight(gB, Wbuf, tid);
    if (tid < 64) {
        const int r = tid >> 1, h = tid & 1;
        float* srow = act1 + r * APAD + h * 64;
        float mx = -1e30f;
#pragma unroll 8
        for (int j = 0; j < 64; j++) mx = fmaxf(mx, srow[j]);
        float sum = 0.f;
#pragma unroll 8
        for (int j = 0; j < 64; j++) { float e = __expf(srow[j] - mx); srow[j] = e; sum += e; }
        float inv = 1.f / sum;
#pragma unroll 8
        for (int j = 0; j < 64; j++) srow[j] *= inv;
    }
    __syncthreads();

    // -------- stage 2: h = relu(alpha @ B + bo) ; write h output + stage to act0 --------
    gemm_tile(act1, Wbuf, acc, rbase, c0);
    {
        float4 b0 = *reinterpret_cast<const float4*>(bo + c0);
        float4 b1 = *reinterpret_cast<const float4*>(bo + 64 + c0);
#pragma unroll
        for (int i = 0; i < 4; i++) {
            float4 h0 = make_float4(fmaxf(acc[i][0] + b0.x, 0.f), fmaxf(acc[i][1] + b0.y, 0.f),
                                    fmaxf(acc[i][2] + b0.z, 0.f), fmaxf(acc[i][3] + b0.w, 0.f));
            float4 h1 = make_float4(fmaxf(acc[i][4] + b1.x, 0.f), fmaxf(acc[i][5] + b1.y, 0.f),
                                    fmaxf(acc[i][6] + b1.z, 0.f), fmaxf(acc[i][7] + b1.w, 0.f));
            const int gr = row0 + rbase + i;
            *reinterpret_cast<float4*>(outH + (size_t)gr * Dn + c0)      = h0;
            *reinterpret_cast<float4*>(outH + (size_t)gr * Dn + 64 + c0) = h1;
            *reinterpret_cast<float4*>(act0 + (rbase + i) * APAD + c0)      = h0;   // act0 free (x dead)
            *reinterpret_cast<float4*>(act0 + (rbase + i) * APAD + 64 + c0) = h1;
        }
    }
    __syncthreads();                 // all stage-2 reads of Wbuf complete
    load_weight(gWfcT, Wbuf, tid);
    __syncthreads();

    // -------- stage 3: preds = h @ WfcT + bfc --------
    gemm_tile(act0, Wbuf, acc, rbase, c0);
    {
        float4 b0 = *reinterpret_cast<const float4*>(bfc + c0);
        float4 b1 = *reinterpret_cast<const float4*>(bfc + 64 + c0);
#pragma unroll
        for (int i = 0; i < 4; i++) {
            float4 p0 = make_float4(acc[i][0] + b0.x, acc[i][1] + b0.y,
                                    acc[i][2] + b0.z, acc[i][3] + b0.w);
            float4 p1 = make_float4(acc[i][4] + b1.x, acc[i][5] + b1.y,
                                    acc[i][6] + b1.z, acc[i][7] + b1.w);
            const int gr = row0 + rbase + i;
            *reinterpret_cast<float4*>(outP + (size_t)gr * Dn + c0)      = p0;
            *reinterpret_cast<float4*>(outP + (size_t)gr * Dn + 64 + c0) = p1;
        }
    }
}

// ============================================================
// launcher (graph-capturable: kernel launches only)
// ============================================================
extern "C" void kernel_launch(void* const* d_in, const int* in_sizes, int n_in,
                              void* d_out, int out_size) {
    const float* x       = (const float*)d_in[0];
    const float* proxies = (const float*)d_in[1];
    const float* Wq  = (const float*)d_in[2];
    const float* bq  = (const float*)d_in[3];
    const float* Wk  = (const float*)d_in[4];
    const float* bk  = (const float*)d_in[5];
    const float* Wv  = (const float*)d_in[6];
    const float* bv  = (const float*)d_in[7];
    const float* Wo  = (const float*)d_in[8];
    const float* bo  = (const float*)d_in[9];
    const float* Wfc = (const float*)d_in[10];
    const float* bfc = (const float*)d_in[11];
    // d_in[12] = edge_index : dense bipartite structure is known -> unused

    float* outP = (float*)d_out;                 // preds[P:]  (S x D)
    float* outH = outP + (size_t)out_size / 2;   // h[P:]      (S x D)

    pre_kv_kernel<<<Pn, NTHR>>>(proxies, Wk, bk, Wv, bv);
    pre_tr_kernel<<<Dn, NTHR>>>(Wo, Wfc);
    pre_ab_kernel<<<Dn, NTHR>>>(Wq, bq);

    const int smem_bytes = (2 * TM * APAD + Dn * Dn) * (int)sizeof(float);  // ~99 KB
    cudaFuncSetAttribute(gnn_main_kernel,
                         cudaFuncAttributeMaxDynamicSharedMemorySize, smem_bytes);
    gnn_main_kernel<<<Sn / TM, NTHR, smem_bytes>>>(x, bo, bfc, outP, outH);
}

// round 9
// speedup vs baseline: 1.0096x; 1.0096x over previous
#include <cuda_runtime.h>

#define Pn   64
#define Sn   4096
#define Dn   128
#define TM   32          // sample rows per block
#define NTHR 128
#define APAD 132         // padded activation row stride (floats) -> conflict-free

// -------- persistent scratch (no allocs allowed) --------
__device__ float gK[Pn * Dn];
__device__ float gV[Pn * Dn];
__device__ float gWoT[Dn * Dn];
__device__ float gWfcT[Dn * Dn];
__device__ float gA[Dn * Dn];     // folded Wq * K^T / 8   (scores = x @ gA + gc)
__device__ float gB[Dn * Dn];     // folded V * Wo^T       (h = alpha @ gB + bo)
__device__ float gc[Dn];          // folded bq * K^T / 8

// ============================================================
// Precompute 1: K = proxies @ Wk^T + bk ; V = proxies @ Wv^T + bv
// grid 64 (one proxy per block), 128 threads (one output dim each)
// ============================================================
__global__ void pre_kv_kernel(const float* __restrict__ proxies,
                              const float* __restrict__ Wk, const float* __restrict__ bk,
                              const float* __restrict__ Wv, const float* __restrict__ bv) {
    __shared__ float pr[Dn];
    const int p = blockIdx.x, t = threadIdx.x;
    pr[t] = proxies[p * Dn + t];
    __syncthreads();
    const float* wk = Wk + t * Dn;
    const float* wv = Wv + t * Dn;
    float a = 0.f, b = 0.f;
#pragma unroll 16
    for (int j = 0; j < Dn; j++) { a += pr[j] * wk[j]; b += pr[j] * wv[j]; }
    gK[p * Dn + t] = a + bk[t];
    gV[p * Dn + t] = b + bv[t];
}

// ============================================================
// Precompute 2: transpose Wo and Wfc (coalesced reads)
// grid 128, 128 threads
// ============================================================
__global__ void pre_tr_kernel(const float* __restrict__ Wo,
                              const float* __restrict__ Wfc) {
    const int b = blockIdx.x, t = threadIdx.x;
    gWoT [t * Dn + b] = Wo [b * Dn + t];   // WoT[d][j]  = Wo[j][d]
    gWfcT[t * Dn + b] = Wfc[b * Dn + t];   // WfcT[d][j] = Wfc[j][d]
}

// ============================================================
// Precompute 3: fold projections into per-proxy matrices.
//   col = h*64 + p
//   gA[d][col] = (1/8) * sum_j Wq[h*64+j][d] * K[p][h*64+j]
//   gc[col]    = (1/8) * sum_j bq[h*64+j]    * K[p][h*64+j]
//   gB[col][j] =         sum_j' V[p][h*64+j'] * Wo[j][h*64+j']
// grid 128 (one col per block), 128 threads
// ============================================================
__global__ void pre_ab_kernel(const float* __restrict__ Wq,
                              const float* __restrict__ bq) {
    __shared__ float kh[64], vh[64], part[64];
    const int col = blockIdx.x, t = threadIdx.x;
    const int h = col >> 6, p = col & 63;
    if (t < 64) {
        float kv = gK[p * Dn + h * 64 + t];
        kh[t] = kv;
        vh[t] = gV[p * Dn + h * 64 + t];
        part[t] = bq[h * 64 + t] * kv;
    }
    __syncthreads();
    float a = 0.f;
#pragma unroll 16
    for (int j = 0; j < 64; j++) a += Wq[(h * 64 + j) * Dn + t] * kh[j];   // coalesced over t
    gA[t * Dn + col] = a * 0.125f;
    float bs = 0.f;
#pragma unroll 16
    for (int j = 0; j < 64; j++) bs += vh[j] * gWoT[(h * 64 + j) * Dn + t]; // coalesced over t
    gB[col * Dn + t] = bs;
    if (t == 0) {
        float cs = 0.f;
        for (int j = 0; j < 64; j++) cs += part[j];
        gc[col] = cs * 0.125f;
    }
}

// ============================================================
// Main fused kernel: 3 chained 32x128x128 GEMM stages + softmax.
// 128 threads: rg = tid>>4 (8 row groups of 4), cg = tid&15 (16 col groups).
// Each thread: 4 rows x 8 cols register tile (cols c0..c0+3 and 64+c0..64+c0+3).
// ============================================================
__device__ __forceinline__ void gemm_tile(const float* __restrict__ Xs,   // [TM][APAD]
                                          const float* __restrict__ Ws,   // [128][128]
                                          float acc[4][8], int rbase, int c0) {
#pragma unroll
    for (int i = 0; i < 4; i++)
#pragma unroll
        for (int j = 0; j < 8; j++) acc[i][j] = 0.f;

    const float* xr = Xs + rbase * APAD;
#pragma unroll 8
    for (int k = 0; k < Dn; k++) {
        float xv[4];
#pragma unroll
        for (int i = 0; i < 4; i++) xv[i] = xr[i * APAD + k];   // broadcast, conflict-free
        float4 w0 = *reinterpret_cast<const float4*>(Ws + k * Dn + c0);
        float4 w1 = *reinterpret_cast<const float4*>(Ws + k * Dn + 64 + c0);
        float wv[8] = {w0.x, w0.y, w0.z, w0.w, w1.x, w1.y, w1.z, w1.w};
#pragma unroll
        for (int i = 0; i < 4; i++)
#pragma unroll
            for (int j = 0; j < 8; j++) acc[i][j] += xv[i] * wv[j];
    }
}

__device__ __forceinline__ void load_weight(const float* __restrict__ gW, float* Wbuf, int tid) {
    const float4* g = reinterpret_cast<const float4*>(gW);
    float4* s = reinterpret_cast<float4*>(Wbuf);
#pragma unroll
    for (int i = 0; i < 32; i++) s[tid + i * NTHR] = g[tid + i * NTHR];
}

__global__ __launch_bounds__(NTHR) void gnn_main_kernel(
    const float* __restrict__ x,
    const float* __restrict__ bo, const float* __restrict__ bfc,
    float* __restrict__ outP, float* __restrict__ outH)
{
    extern __shared__ float smem[];
    float* act0 = smem;                       // TM*APAD : x tile, later h tile
    float* act1 = smem + TM * APAD;           // TM*APAD : scores -> alpha
    float* Wbuf = smem + 2 * TM * APAD;       // 128*128 : A, then B, then WfcT

    const int tid   = threadIdx.x;
    const int row0  = blockIdx.x * TM;
    const int rg    = tid >> 4;
    const int cg    = tid & 15;
    const int rbase = rg * 4;
    const int c0    = cg * 4;

    // -------- load x tile (row-major, padded) + A --------
    {
        const float4* xg = reinterpret_cast<const float4*>(x + (size_t)row0 * Dn);
#pragma unroll
        for (int i = 0; i < 8; i++) {
            int idx = tid + i * NTHR;          // float4 index within 32x128 tile
            int r = idx >> 5, c4 = idx & 31;
            float4 v = xg[idx];
            *reinterpret_cast<float4*>(act0 + r * APAD + c4 * 4) = v;
        }
        load_weight(gA, Wbuf, tid);
    }
    __syncthreads();

    float acc[4][8];

    // -------- stage 1: scores = x @ A + c --------
    gemm_tile(act0, Wbuf, acc, rbase, c0);
    {
        float4 cv0 = *reinterpret_cast<const float4*>(gc + c0);
        float4 cv1 = *reinterpret_cast<const float4*>(gc + 64 + c0);
#pragma unroll
        for (int i = 0; i < 4; i++) {
            float4 s0 = make_float4(acc[i][0] + cv0.x, acc[i][1] + cv0.y,
                                    acc[i][2] + cv0.z, acc[i][3] + cv0.w);
            float4 s1 = make_float4(acc[i][4] + cv1.x, acc[i][5] + cv1.y,
                                    acc[i][6] + cv1.z, acc[i][7] + cv1.w);
            *reinterpret_cast<float4*>(act1 + (rbase + i) * APAD + c0)      = s0;
            *reinterpret_cast<float4*>(act1 + (rbase + i) * APAD + 64 + c0) = s1;
        }
    }
    __syncthreads();

    // -------- load B (all threads) + per-(row,head) softmax over 64 proxies --------
    load_weight(gB, Wbuf, tid);
    if (tid < 64) {
        const int r = tid >> 1, h = tid & 1;
        float* srow = act1 + r * APAD + h * 64;
        float mx = -1e30f;
#pragma unroll 8
        for (int j = 0; j < 64; j++) mx = fmaxf(mx, srow[j]);
        float sum = 0.f;
#pragma unroll 8
        for (int j = 0; j < 64; j++) { float e = __expf(srow[j] - mx); srow[j] = e; sum += e; }
        float inv = 1.f / sum;
#pragma unroll 8
        for (int j = 0; j < 64; j++) srow[j] *= inv;
    }
    __syncthreads();

    // -------- stage 2: h = relu(alpha @ B + bo) ; write h output + stage to act0 --------
    gemm_tile(act1, Wbuf, acc, rbase, c0);
    {
        float4 b0 = *reinterpret_cast<const float4*>(bo + c0);
        float4 b1 = *reinterpret_cast<const float4*>(bo + 64 + c0);
#pragma unroll
        for (int i = 0; i < 4; i++) {
            float4 h0 = make_float4(fmaxf(acc[i][0] + b0.x, 0.f), fmaxf(acc[i][1] + b0.y, 0.f),
                                    fmaxf(acc[i][2] + b0.z, 0.f), fmaxf(acc[i][3] + b0.w, 0.f));
            float4 h1 = make_float4(fmaxf(acc[i][4] + b1.x, 0.f), fmaxf(acc[i][5] + b1.y, 0.f),
                                    fmaxf(acc[i][6] + b1.z, 0.f), fmaxf(acc[i][7] + b1.w, 0.f));
            const int gr = row0 + rbase + i;
            *reinterpret_cast<float4*>(outH + (size_t)gr * Dn + c0)      = h0;
            *reinterpret_cast<float4*>(outH + (size_t)gr * Dn + 64 + c0) = h1;
            *reinterpret_cast<float4*>(act0 + (rbase + i) * APAD + c0)      = h0;   // act0 free (x dead)
            *reinterpret_cast<float4*>(act0 + (rbase + i) * APAD + 64 + c0) = h1;
        }
    }
    __syncthreads();                 // all stage-2 reads of Wbuf complete
    load_weight(gWfcT, Wbuf, tid);
    __syncthreads();

    // -------- stage 3: preds = h @ WfcT + bfc --------
    gemm_tile(act0, Wbuf, acc, rbase, c0);
    {
        float4 b0 = *reinterpret_cast<const float4*>(bfc + c0);
        float4 b1 = *reinterpret_cast<const float4*>(bfc + 64 + c0);
#pragma unroll
        for (int i = 0; i < 4; i++) {
            float4 p0 = make_float4(acc[i][0] + b0.x, acc[i][1] + b0.y,
                                    acc[i][2] + b0.z, acc[i][3] + b0.w);
            float4 p1 = make_float4(acc[i][4] + b1.x, acc[i][5] + b1.y,
                                    acc[i][6] + b1.z, acc[i][7] + b1.w);
            const int gr = row0 + rbase + i;
            *reinterpret_cast<float4*>(outP + (size_t)gr * Dn + c0)      = p0;
            *reinterpret_cast<float4*>(outP + (size_t)gr * Dn + 64 + c0) = p1;
        }
    }
}

// ============================================================
// launcher (graph-capturable: kernel launches only)
// ============================================================
extern "C" void kernel_launch(void* const* d_in, const int* in_sizes, int n_in,
                              void* d_out, int out_size) {
    const float* x       = (const float*)d_in[0];
    const float* proxies = (const float*)d_in[1];
    const float* Wq  = (const float*)d_in[2];
    const float* bq  = (const float*)d_in[3];
    const float* Wk  = (const float*)d_in[4];
    const float* bk  = (const float*)d_in[5];
    const float* Wv  = (const float*)d_in[6];
    const float* bv  = (const float*)d_in[7];
    const float* Wo  = (const float*)d_in[8];
    const float* bo  = (const float*)d_in[9];
    const float* Wfc = (const float*)d_in[10];
    const float* bfc = (const float*)d_in[11];
    // d_in[12] = edge_index : dense bipartite structure is known -> unused

    float* outP = (float*)d_out;                 // preds[P:]  (S x D)
    float* outH = outP + (size_t)out_size / 2;   // h[P:]      (S x D)

    pre_kv_kernel<<<Pn, NTHR>>>(proxies, Wk, bk, Wv, bv);
    pre_tr_kernel<<<Dn, NTHR>>>(Wo, Wfc);
    pre_ab_kernel<<<Dn, NTHR>>>(Wq, bq);

    const int smem_bytes = (2 * TM * APAD + Dn * Dn) * (int)sizeof(float);  // ~99 KB
    cudaFuncSetAttribute(gnn_main_kernel,
                         cudaFuncAttributeMaxDynamicSharedMemorySize, smem_bytes);
    gnn_main_kernel<<<Sn / TM, NTHR, smem_bytes>>>(x, bo, bfc, outP, outH);
}

// round 10
// speedup vs baseline: 1.9531x; 1.9346x over previous
#include <cuda_runtime.h>
#include <cstdint>

#define Pn   64
#define Sn   4096
#define Dn   128
#define TM   32          // sample rows per block
#define NTHR 256
#define RPAD 36          // padded k-major activation col stride (rows+pad), 144B = 16B aligned

// -------- persistent folded weights (no allocs allowed) --------
__device__ float gA[Dn * Dn];     // gA[d][col] : scores = x @ gA + gc
__device__ float gB[Dn * Dn];     // gB[col][j] : h = relu(alpha @ gB + bo)
__device__ float gWfcT[Dn * Dn];  // gWfcT[k][c] = Wfc[c][k]
__device__ float gc[Dn];          // folded bq * K^T / 8

// ---------------- f32x2 packed helpers ----------------
__device__ __forceinline__ unsigned long long pack2(float lo, float hi) {
    unsigned long long d;
    asm("mov.b64 %0, {%1, %2};" : "=l"(d)
        : "r"(__float_as_uint(lo)), "r"(__float_as_uint(hi)));
    return d;
}
__device__ __forceinline__ void unpack2(unsigned long long v, float& lo, float& hi) {
    unsigned a, b;
    asm("mov.b64 {%0, %1}, %2;" : "=r"(a), "=r"(b) : "l"(v));
    lo = __uint_as_float(a); hi = __uint_as_float(b);
}
#define FMA2(d, a, b) asm("fma.rn.f32x2 %0, %1, %2, %0;" : "+l"(d) : "l"(a), "l"(b))
#define ADD2(d, a)    asm("add.rn.f32x2 %0, %0, %1;"     : "+l"(d) : "l"(a))
#define CP_COMMIT()   asm volatile("cp.async.commit_group;" ::: "memory")
#define CP_WAIT0()    asm volatile("cp.async.wait_group 0;" ::: "memory")

// ============================================================
// Single precompute kernel: grid = 128 (one col = (h,p) each), 256 threads.
//   kh[j] = proxies[p] . Wk[h*64+j] + bk ;  vh[j] likewise with Wv
//   gA[d][col] = 1/8 sum_j Wq[h*64+j][d] * kh[j]
//   gc[col]    = 1/8 sum_j bq[h*64+j]    * kh[j]
//   gB[col][j] =     sum_j' vh[j'] * Wo[j][h*64+j']
//   gWfcT[d][col] = Wfc[col][d]
// ============================================================
__global__ __launch_bounds__(NTHR) void pre_all_kernel(
    const float* __restrict__ proxies,
    const float* __restrict__ Wq, const float* __restrict__ bq,
    const float* __restrict__ Wk, const float* __restrict__ bk,
    const float* __restrict__ Wv, const float* __restrict__ bv,
    const float* __restrict__ Wo, const float* __restrict__ Wfc)
{
    __shared__ __align__(16) float prS[Dn];
    __shared__ __align__(16) float kh[64];
    __shared__ __align__(16) float vh[64];

    const int col = blockIdx.x;
    const int h = col >> 6, p = col & 63;
    const int t = threadIdx.x;
    const int w = t >> 5, l = t & 31;

    if (t < 32)
        *reinterpret_cast<float4*>(prS + t * 4) =
            reinterpret_cast<const float4*>(proxies + p * Dn)[t];
    __syncthreads();

    // warp-cooperative dots: warps 0-3 -> kh, warps 4-7 -> vh (16 j's each)
    {
        const float* Wsrc = (w < 4) ? Wk : Wv;
        const float* bsrc = (w < 4) ? bk : bv;
        float* dst = (w < 4) ? kh : vh;
        const int j0 = (w & 3) * 16;
        float4 pv = *reinterpret_cast<const float4*>(prS + l * 4);
#pragma unroll
        for (int jj = 0; jj < 16; jj++) {
            int j = j0 + jj;
            float4 w4 = *reinterpret_cast<const float4*>(Wsrc + (h * 64 + j) * Dn + l * 4);
            float s = w4.x * pv.x + w4.y * pv.y + w4.z * pv.z + w4.w * pv.w;
#pragma unroll
            for (int o = 16; o; o >>= 1) s += __shfl_xor_sync(0xffffffffu, s, o);
            if (l == 0) dst[j] = s + bsrc[h * 64 + j];
        }
    }
    __syncthreads();

    if (w == 0) {   // gc[col]
        float s = bq[h * 64 + l] * kh[l] + bq[h * 64 + 32 + l] * kh[32 + l];
#pragma unroll
        for (int o = 16; o; o >>= 1) s += __shfl_xor_sync(0xffffffffu, s, o);
        if (l == 0) gc[col] = s * 0.125f;
    }

    if (t < Dn) {   // gA column + WfcT column
        float a = 0.f;
#pragma unroll 16
        for (int j = 0; j < 64; j++) a += Wq[(h * 64 + j) * Dn + t] * kh[j];  // coalesced over t
        gA[t * Dn + col] = a * 0.125f;
        gWfcT[t * Dn + col] = Wfc[col * Dn + t];
    } else {        // gB row
        const int j2 = t - Dn;
        const float4* wo = reinterpret_cast<const float4*>(Wo + j2 * Dn + h * 64);
        float s = 0.f;
#pragma unroll
        for (int q = 0; q < 16; q++) {
            float4 w4 = wo[q];
            float4 v4 = *reinterpret_cast<const float4*>(vh + q * 4);
            s += w4.x * v4.x + w4.y * v4.y + w4.z * v4.z + w4.w * v4.w;
        }
        gB[col * Dn + j2] = s;
    }
}

// ============================================================
// Main kernel helpers
// ============================================================
__device__ __forceinline__ void lw_async(float* Wbuf, const float* __restrict__ gW, int tid) {
    unsigned saddr = (unsigned)__cvta_generic_to_shared(Wbuf);
#pragma unroll
    for (int i = 0; i < 16; i++) {
        int idx = tid + i * NTHR;   // float4 index, 4096 total
        asm volatile("cp.async.cg.shared.global [%0], [%1], 16;"
                     :: "r"(saddr + idx * 16), "l"(gW + idx * 4));
    }
}

// k-major GEMM: out[r][c] = sum_k actT[k][r] * Ws[k*128+c]
// lane owns rows rbase..rbase+7 (packed as 4 f32x2 row-pairs) x cols {c0, c0+1}
__device__ __forceinline__ void gemm_t(const float* __restrict__ actT,
                                       const float* __restrict__ Ws,
                                       int rbase, int c0, unsigned long long acc[8])
{
#pragma unroll
    for (int i = 0; i < 8; i++) acc[i] = 0ull;
#pragma unroll 8
    for (int k = 0; k < Dn; k++) {
        ulonglong2 xa = *reinterpret_cast<const ulonglong2*>(actT + k * RPAD + rbase);
        ulonglong2 xb = *reinterpret_cast<const ulonglong2*>(actT + k * RPAD + rbase + 4);
        float2 wv = *reinterpret_cast<const float2*>(Ws + k * Dn + c0);
        unsigned long long w0d = pack2(wv.x, wv.x);
        unsigned long long w1d = pack2(wv.y, wv.y);
        FMA2(acc[0], xa.x, w0d); FMA2(acc[1], xa.y, w0d);
        FMA2(acc[2], xb.x, w0d); FMA2(acc[3], xb.y, w0d);
        FMA2(acc[4], xa.x, w1d); FMA2(acc[5], xa.y, w1d);
        FMA2(acc[6], xb.x, w1d); FMA2(acc[7], xb.y, w1d);
    }
}

__device__ __forceinline__ void store_packed_col(float* actT, int c, int rbase,
                                                 const unsigned long long* a4) {
    ulonglong2 t0, t1;
    t0.x = a4[0]; t0.y = a4[1];
    t1.x = a4[2]; t1.y = a4[3];
    *reinterpret_cast<ulonglong2*>(actT + c * RPAD + rbase)     = t0;
    *reinterpret_cast<ulonglong2*>(actT + c * RPAD + rbase + 4) = t1;
}

// ============================================================
// Main fused kernel: 3 chained 32x128x128 GEMM stages + softmax.
// 256 threads; warp w owns cols [16w,16w+16); double-buffered weights via cp.async.
// ============================================================
__global__ __launch_bounds__(NTHR) void gnn_main_kernel(
    const float* __restrict__ x,
    const float* __restrict__ bo, const float* __restrict__ bfc,
    float* __restrict__ outP, float* __restrict__ outH)
{
    extern __shared__ float smem[];
    float* actT0 = smem;                    // [128][RPAD]  x tile (k-major), later hT
    float* actT1 = smem + Dn * RPAD;        // [128][RPAD]  scoresT -> alphaT
    float* W0    = smem + 2 * Dn * RPAD;    // 128*128
    float* W1    = W0 + Dn * Dn;

    const int tid  = threadIdx.x;
    const int row0 = blockIdx.x * TM;
    const int w = tid >> 5, l = tid & 31;
    const int c0    = w * 16 + (l & 7) * 2;
    const int rbase = (l >> 3) * 8;

    // -------- prologue: cp.async A -> W0 ; stage x transposed into actT0 --------
    lw_async(W0, gA, tid);
    CP_COMMIT();
    {
        const float4* xg = reinterpret_cast<const float4*>(x + (size_t)row0 * Dn);
#pragma unroll
        for (int i = 0; i < 4; i++) {
            int idx = tid + i * NTHR;       // 0..1023 float4 of 32x128 tile
            int r = idx >> 5, c4 = idx & 31;
            float4 v = xg[idx];
            actT0[(c4 * 4 + 0) * RPAD + r] = v.x;
            actT0[(c4 * 4 + 1) * RPAD + r] = v.y;
            actT0[(c4 * 4 + 2) * RPAD + r] = v.z;
            actT0[(c4 * 4 + 3) * RPAD + r] = v.w;
        }
    }
    CP_WAIT0();
    __syncthreads();

    unsigned long long acc[8];

    // -------- stage 1: scoresT = (x @ A + c)^T ; prefetch B -> W1 --------
    lw_async(W1, gB, tid);
    CP_COMMIT();
    gemm_t(actT0, W0, rbase, c0, acc);
    {
        float2 cv = *reinterpret_cast<const float2*>(gc + c0);
        unsigned long long cd0 = pack2(cv.x, cv.x);
        unsigned long long cd1 = pack2(cv.y, cv.y);
        ADD2(acc[0], cd0); ADD2(acc[1], cd0); ADD2(acc[2], cd0); ADD2(acc[3], cd0);
        ADD2(acc[4], cd1); ADD2(acc[5], cd1); ADD2(acc[6], cd1); ADD2(acc[7], cd1);
        store_packed_col(actT1, c0,     rbase, acc);
        store_packed_col(actT1, c0 + 1, rbase, acc + 4);
    }
    CP_WAIT0();
    __syncthreads();

    // -------- prefetch WfcT -> W0 (stage-1 readers of W0 are done) ; softmax --------
    lw_async(W0, gWfcT, tid);
    CP_COMMIT();
    if (tid < 64) {                          // one (row, head) per thread
        const int r = tid >> 1, hh = tid & 1;
        float* sp = actT1 + (hh * 64) * RPAD + r;
        float mx = -1e30f;
#pragma unroll 8
        for (int p = 0; p < 64; p++) mx = fmaxf(mx, sp[p * RPAD]);
        float sum = 0.f;
#pragma unroll 8
        for (int p = 0; p < 64; p++) { float e = __expf(sp[p * RPAD] - mx); sp[p * RPAD] = e; sum += e; }
        float inv = 1.f / sum;
#pragma unroll 8
        for (int p = 0; p < 64; p++) sp[p * RPAD] *= inv;
    }
    __syncthreads();

    // -------- stage 2: h = relu(alpha @ B + bo) ; write outH + hT -> actT0 --------
    gemm_t(actT1, W1, rbase, c0, acc);
    {
        float2 bv = *reinterpret_cast<const float2*>(bo + c0);
        float h0[8], h1[8];
#pragma unroll
        for (int rp = 0; rp < 4; rp++) {
            float a, b;
            unpack2(acc[rp], a, b);
            h0[2 * rp]     = fmaxf(a + bv.x, 0.f);
            h0[2 * rp + 1] = fmaxf(b + bv.x, 0.f);
            unpack2(acc[4 + rp], a, b);
            h1[2 * rp]     = fmaxf(a + bv.y, 0.f);
            h1[2 * rp + 1] = fmaxf(b + bv.y, 0.f);
        }
        *reinterpret_cast<float4*>(actT0 + c0 * RPAD + rbase)
            = make_float4(h0[0], h0[1], h0[2], h0[3]);
        *reinterpret_cast<float4*>(actT0 + c0 * RPAD + rbase + 4)
            = make_float4(h0[4], h0[5], h0[6], h0[7]);
        *reinterpret_cast<float4*>(actT0 + (c0 + 1) * RPAD + rbase)
            = make_float4(h1[0], h1[1], h1[2], h1[3]);
        *reinterpret_cast<float4*>(actT0 + (c0 + 1) * RPAD + rbase + 4)
            = make_float4(h1[4], h1[5], h1[6], h1[7]);
#pragma unroll
        for (int rr = 0; rr < 8; rr++)
            *reinterpret_cast<float2*>(outH + (size_t)(row0 + rbase + rr) * Dn + c0)
                = make_float2(h0[rr], h1[rr]);
    }
    CP_WAIT0();                              // WfcT landed (overlapped with stage 2)
    __syncthreads();

    // -------- stage 3: preds = h @ Wfc^T + bfc --------
    gemm_t(actT0, W0, rbase, c0, acc);
    {
        float2 bv = *reinterpret_cast<const float2*>(bfc + c0);
#pragma unroll
        for (int rp = 0; rp < 4; rp++) {
            float a, b, a1, b1;
            unpack2(acc[rp], a, b);
            unpack2(acc[4 + rp], a1, b1);
            *reinterpret_cast<float2*>(outP + (size_t)(row0 + rbase + 2 * rp) * Dn + c0)
                = make_float2(a + bv.x, a1 + bv.y);
            *reinterpret_cast<float2*>(outP + (size_t)(row0 + rbase + 2 * rp + 1) * Dn + c0)
                = make_float2(b + bv.x, b1 + bv.y);
        }
    }
}

// ============================================================
// launcher (graph-capturable: kernel launches only)
// ============================================================
extern "C" void kernel_launch(void* const* d_in, const int* in_sizes, int n_in,
                              void* d_out, int out_size) {
    const float* x       = (const float*)d_in[0];
    const float* proxies = (const float*)d_in[1];
    const float* Wq  = (const float*)d_in[2];
    const float* bq  = (const float*)d_in[3];
    const float* Wk  = (const float*)d_in[4];
    const float* bk  = (const float*)d_in[5];
    const float* Wv  = (const float*)d_in[6];
    const float* bv  = (const float*)d_in[7];
    const float* Wo  = (const float*)d_in[8];
    const float* bo  = (const float*)d_in[9];
    const float* Wfc = (const float*)d_in[10];
    const float* bfc = (const float*)d_in[11];
    // d_in[12] = edge_index : dense bipartite structure is known -> unused

    float* outP = (float*)d_out;                 // preds[P:]  (S x D)
    float* outH = outP + (size_t)out_size / 2;   // h[P:]      (S x D)

    pre_all_kernel<<<Dn, NTHR>>>(proxies, Wq, bq, Wk, bk, Wv, bv, Wo, Wfc);

    const int smem_bytes = (2 * Dn * RPAD + 2 * Dn * Dn) * (int)sizeof(float);  // ~164 KB
    cudaFuncSetAttribute(gnn_main_kernel,
                         cudaFuncAttributeMaxDynamicSharedMemorySize, smem_bytes);
    gnn_main_kernel<<<Sn / TM, NTHR, smem_bytes>>>(x, bo, bfc, outP, outH);
}